// round 16
// baseline (speedup 1.0000x reference)
#include <cuda_runtime.h>
#include <cuda_fp16.h>
#include <cstdint>
#include <math.h>

#define BB 4096
#define NN 32
#define HH 256
#define RR 3
#define VDECAY 0.7f

// ---------------- device scratch ----------------
__device__ float  g_csum6[6 * BB * HH];        // [r*2+khalf][b][g] partial csum
__device__ __half g_chH[(size_t)BB * NN * HH]; // child_h fp16 (raw)
__device__ __half g_combH[BB * 512];           // comb fp16 hi
__device__ __half g_combL[BB * 512];           // comb fp16 lo
__device__ __half g_WfH[RR * HH * HH];         // W_f fp16 hi
__device__ __half g_WfL[RR * HH * HH];         // W_f fp16 lo
__device__ __half g_WgH[3 * HH * 512];         // gate W fp16 hi [gate][g][k]
__device__ __half g_WgL[3 * HH * 512];         // gate W fp16 lo

// ---------------- helpers ----------------
__device__ __forceinline__ uint32_t smem_u32(const void* p) {
    uint32_t a;
    asm("{ .reg .u64 t; cvta.to.shared.u64 t, %1; cvt.u32.u64 %0, t; }" : "=r"(a) : "l"(p));
    return a;
}
__device__ __forceinline__ void ldsm4(uint32_t* r, uint32_t addr) {
    asm volatile("ldmatrix.sync.aligned.m8n8.x4.shared.b16 {%0,%1,%2,%3}, [%4];"
                 : "=r"(r[0]), "=r"(r[1]), "=r"(r[2]), "=r"(r[3]) : "r"(addr));
}
__device__ __forceinline__ void mma16816h(float* d, const uint32_t* a, const uint32_t* b) {
    asm volatile("mma.sync.aligned.m16n8k16.row.col.f32.f16.f16.f32 "
                 "{%0,%1,%2,%3},{%4,%5,%6,%7},{%8,%9},{%0,%1,%2,%3};"
                 : "+f"(d[0]), "+f"(d[1]), "+f"(d[2]), "+f"(d[3])
                 : "r"(a[0]), "r"(a[1]), "r"(a[2]), "r"(a[3]), "r"(b[0]), "r"(b[1]));
}
__device__ __forceinline__ uint32_t pkhf(float x, float y) {
    __half2 t = __floats2half2_rn(x, y);
    return *(uint32_t*)&t;
}
__device__ __forceinline__ void cpa16(void* sdst, const void* gsrc) {
    unsigned s = (unsigned)__cvta_generic_to_shared(sdst);
    asm volatile("cp.async.ca.shared.global [%0], [%1], 16;" :: "r"(s), "l"(gsrc) : "memory");
}
#define CPA_COMMIT() asm volatile("cp.async.commit_group;" ::: "memory")
template <int N> __device__ __forceinline__ void cpa_wait() {
    asm volatile("cp.async.wait_group %0;" :: "n"(N) : "memory");
}

// ---------------- prep: fp16 splits for W_f and gate weights ----------------
__global__ void prep_kernel(const float* __restrict__ Wi,
                            const float* __restrict__ Wo,
                            const float* __restrict__ Wu,
                            const float* __restrict__ Wf) {
    int idx = blockIdx.x * blockDim.x + threadIdx.x;
    const int NWG = 3 * HH * 512;    // 393216
    const int NF  = RR * HH * HH;    // 196608
    if (idx < NWG) {
        int j = idx & (HH * 512 - 1);
        int gate = idx >> 17;
        const float* W = (gate == 0) ? Wi : ((gate == 1) ? Wo : Wu);
        float v = W[j];
        __half h = __float2half_rn(v);
        g_WgH[idx] = h;
        g_WgL[idx] = __float2half_rn(v - __half2float(h));
    } else if (idx < NWG + NF) {
        int j = idx - NWG;
        float v = Wf[j];
        __half h = __float2half_rn(v);
        g_WfH[j] = h;
        g_WfL[j] = __float2half_rn(v - __half2float(h));
    }
}

// ---------------- attention + comb + fp16 conversions (validated R15) ----------------
#define CHS 260
__global__ __launch_bounds__(256) void attn_kernel(
    const float* __restrict__ input_vec, const float* __restrict__ child_h,
    const int* __restrict__ relation_ids, const int* __restrict__ virtual_mask,
    const float* __restrict__ rel_emb, const float* __restrict__ w_att,
    const float* __restrict__ b_att)
{
    __shared__ float sh_ch[NN * CHS];
    __shared__ int   sh_rid[NN];
    __shared__ float sh_decay[NN], sh_score[NN], sh_attn[NN];
    const int b = blockIdx.x, tid = threadIdx.x, lane = tid & 31, warp = tid >> 5;

    if (tid < NN) {
        sh_rid[tid]   = relation_ids[b * NN + tid];
        sh_decay[tid] = virtual_mask[b * NN + tid] ? VDECAY : 1.0f;
    }
    __syncthreads();
    {
        const float* chb = child_h + (size_t)b * NN * HH;
        uint32_t* chH2 = (uint32_t*)(g_chH + (size_t)b * NN * HH);
        for (int i2 = tid; i2 < NN * 128; i2 += 256) {
            int n = i2 >> 7, h2 = (i2 & 127) * 2;
            float2 v = *(const float2*)(chb + n * HH + h2);
            float d = sh_decay[n];
            sh_ch[n * CHS + h2]     = v.x * d;
            sh_ch[n * CHS + h2 + 1] = v.y * d;
            chH2[i2] = pkhf(v.x, v.y);
        }
    }
    __syncthreads();
    {
        float batt = b_att[0];
        #pragma unroll
        for (int c = 0; c < 4; c++) {
            int p = warp * 4 + c;
            int r = sh_rid[p];
            float s = 0.0f;
            #pragma unroll
            for (int j = 0; j < 8; j++) {
                int h = j * 32 + lane;
                s = fmaf(rel_emb[r * HH + h] + sh_ch[p * CHS + h], w_att[h], s);
            }
            #pragma unroll
            for (int off = 16; off; off >>= 1) s += __shfl_xor_sync(0xffffffffu, s, off);
            if (lane == 0) sh_score[p] = s + batt;
        }
    }
    __syncthreads();
    if (warp == 0) {
        float v = sh_score[lane], m = v;
        #pragma unroll
        for (int off = 16; off; off >>= 1) m = fmaxf(m, __shfl_xor_sync(0xffffffffu, m, off));
        float e = expf(v - m), s = e;
        #pragma unroll
        for (int off = 16; off; off >>= 1) s += __shfl_xor_sync(0xffffffffu, s, off);
        sh_attn[lane] = e / s;
    }
    __syncthreads();
    const int g = tid;
    float hs = 0.0f;
    #pragma unroll
    for (int p = 0; p < NN; p++) hs = fmaf(sh_attn[p], sh_ch[p * CHS + g], hs);
    float inv = input_vec[(size_t)b * HH + g];
    __half ih = __float2half_rn(inv);
    __half hh = __float2half_rn(hs);
    g_combH[b * 512 + g]       = ih;
    g_combL[b * 512 + g]       = __float2half_rn(inv - __half2float(ih));
    g_combH[b * 512 + 256 + g] = hh;
    g_combL[b * 512 + 256 + g] = __float2half_rn(hs - __half2float(hh));
}

// ---------------- fgemm_mma: fp16 2-term, cp.async pipelined (R14/15, validated) ----
#define BSTR 136
#define BL_OFF 34816
#define AB_OFF(buf) ((buf) * 8704)
#define F_OFF 17408
#define FSTR 132
#define FG_DYN 69632

__global__ __launch_bounds__(256, 2) void fgemm_mma(
    const float* __restrict__ child_c,
    const int*   __restrict__ relation_ids,
    const int*   __restrict__ virtual_mask,
    const float* __restrict__ b_f)
{
    extern __shared__ char dsm[];
    __shared__ int   sList[512], sStart[17], sCnt[16];
    __shared__ float shCS[2][16][129];

    const int tid = threadIdx.x, lane = tid & 31, warp = tid >> 5;
    const int b0 = blockIdx.x * 16, r = blockIdx.y;
    const int ghalf = blockIdx.z & 1, khalf = blockIdx.z >> 1;
    const int g0 = ghalf * 128, k0 = khalf * 128;

    if (tid < 16) {
        int c = 0;
        for (int n = 0; n < 32; n++) c += (relation_ids[(b0 + tid) * NN + n] == r);
        sCnt[tid] = c;
    }
    for (int i = tid; i < 2 * 16 * 129; i += 256) ((float*)shCS)[i] = 0.0f;
    __syncthreads();
    if (tid == 0) {
        int a = 0;
        for (int i = 0; i < 16; i++) { sStart[i] = a; a += sCnt[i]; }
        sStart[16] = a;
    }
    __syncthreads();
    if (tid < 16) {
        int pos = sStart[tid];
        for (int n = 0; n < 32; n++) {
            if (relation_ids[(b0 + tid) * NN + n] == r) {
                int v = virtual_mask[(b0 + tid) * NN + n] ? 1 : 0;
                sList[pos++] = n | (v << 6) | (tid << 8);
            }
        }
    }
    __syncthreads();

    for (int j = tid; j < 4096; j += 256) {
        int hl = j >> 11, jj = j & 2047;
        int gg = jj >> 4, q = jj & 15;
        const __half* src = (hl ? g_WfL : g_WfH) +
            (size_t)r * 65536 + (size_t)(g0 + gg) * 256 + k0 + q * 8;
        cpa16(dsm + hl * BL_OFF + (gg * BSTR + q * 8) * 2, src);
    }
    CPA_COMMIT();
    cpa_wait<0>();
    __syncthreads();

    const int count = sStart[16];
    const int ntiles = (count + 31) >> 5;
    const uint32_t smb = smem_u32(dsm);
    const int gcol = tid & 127, hf = tid >> 7;
    const float bfk = (khalf == 0) ? b_f[r * HH + g0 + gcol] : 0.0f;
    const int tIdx = lane >> 3, rsub = lane & 7;

    uint32_t bhreg[8][4];
    {
        int n = warp * 16 + ((tIdx & 2) ? 8 : 0) + rsub;
        #pragma unroll
        for (int kt = 0; kt < 8; kt++) {
            int k = kt * 16 + ((tIdx & 1) ? 8 : 0);
            ldsm4(bhreg[kt], smb + (uint32_t)(n * BSTR + k) * 2u);
        }
    }
    __syncthreads();

    auto stageA = [&](int tt, int buf) {
        for (int i = tid; i < 512; i += 256) {
            int s = i >> 4, q = i & 15;
            int gs = tt * 32 + s;
            if (gs < count) {
                int e = sList[gs];
                const __half* src = g_chH +
                    (((size_t)(b0 + (e >> 8))) * NN + (e & 63)) * HH + k0 + q * 8;
                cpa16(dsm + AB_OFF(buf) + (s * BSTR + q * 8) * 2, src);
            }
        }
        CPA_COMMIT();
    };

    if (ntiles > 0) stageA(0, 0);

    for (int t = 0; t < ntiles; t++) {
        const int buf = t & 1;
        cpa_wait<0>();
        __syncthreads();

        if (t + 1 < ntiles) stageA(t + 1, buf ^ 1);

        float ccv[16];
        {
            int sbase = t * 32 + hf * 16;
            #pragma unroll
            for (int j = 0; j < 16; j++) {
                int s = sbase + j;
                float v = 0.0f;
                if (s < count) {
                    int e = sList[s];
                    v = child_c[((size_t)(b0 + (e >> 8)) * NN + (e & 63)) * HH + g0 + gcol];
                }
                ccv[j] = v;
            }
        }

        float d[2][2][4];
        #pragma unroll
        for (int mt = 0; mt < 2; mt++)
            #pragma unroll
            for (int nt = 0; nt < 2; nt++)
                #pragma unroll
                for (int q = 0; q < 4; q++) d[mt][nt][q] = 0.0f;
        {
            const uint32_t ahb = smb + AB_OFF(buf);
            const uint32_t blb = smb + BL_OFF;
            int brow = warp * 16 + ((tIdx & 2) ? 8 : 0) + rsub;
            #pragma unroll
            for (int kt = 0; kt < 8; kt++) {
                int kk = kt * 16;
                int kfrag = kk + ((tIdx & 1) ? 8 : 0);
                uint32_t areg[2][4], blreg[4];
                #pragma unroll
                for (int mt = 0; mt < 2; mt++) {
                    int row = mt * 16 + ((tIdx & 1) ? 8 : 0) + rsub;
                    int col = kk + ((tIdx & 2) ? 8 : 0);
                    ldsm4(areg[mt], ahb + (uint32_t)(row * BSTR + col) * 2u);
                }
                ldsm4(blreg, blb + (uint32_t)(brow * BSTR + kfrag) * 2u);
                #pragma unroll
                for (int mt = 0; mt < 2; mt++)
                    #pragma unroll
                    for (int nt = 0; nt < 2; nt++) {
                        mma16816h(d[mt][nt], areg[mt], &bhreg[kt][nt * 2]);
                        mma16816h(d[mt][nt], areg[mt], &blreg[nt * 2]);
                    }
            }
        }

        {
            float* F = (float*)(dsm + F_OFF);
            int arow = lane >> 2, acol = (lane & 3) * 2;
            #pragma unroll
            for (int mt = 0; mt < 2; mt++)
                #pragma unroll
                for (int nt = 0; nt < 2; nt++) {
                    int col = warp * 16 + nt * 8 + acol;
                    F[(mt * 16 + arow) * FSTR + col]         = d[mt][nt][0];
                    F[(mt * 16 + arow) * FSTR + col + 1]     = d[mt][nt][1];
                    F[(mt * 16 + arow + 8) * FSTR + col]     = d[mt][nt][2];
                    F[(mt * 16 + arow + 8) * FSTR + col + 1] = d[mt][nt][3];
                }
        }
        __syncthreads();

        {
            const float* F = (const float*)(dsm + F_OFF);
            int sbase = t * 32 + hf * 16;
            int smax = min(16, count - sbase);
            for (int j = 0; j < smax; j++) {
                int e = sList[sbase + j];
                int bl = e >> 8;
                float dcy = ((e >> 6) & 1) ? VDECAY : 1.0f;
                float Fv = F[(hf * 16 + j) * FSTR + gcol];
                shCS[hf][bl][gcol] += (Fv * dcy + bfk) * (ccv[j] * dcy);
            }
        }
    }

    {
        int slot = r * 2 + khalf;
        __syncthreads();
        for (int i = tid; i < 16 * 128; i += 256) {
            int bl = i >> 7, g = i & 127;
            g_csum6[((size_t)slot * BB + b0 + bl) * HH + g0 + g] =
                shCS[0][bl][g] + shCS[1][bl][g];
        }
    }
}

// ---------------- gates_fused: 3-gate HMMA + inline epilogue ----------------
// grid (128, 2): x = batch tile (32), y = ghalf. block 256 = 8 warps, 2 CTAs/SM.
// dyn smem 107520: A_HI @0 (33280), A_LO @33280; B @66560: (buf*2+hl)*10240, [128 n][40 k]
#define GASTR 520
#define GA_LO 33280
#define GB_OFF(buf, hl) (66560 + ((buf) * 2 + (hl)) * 10240)
#define GBSTR 40
#define GF_DYN 107520

__global__ __launch_bounds__(256, 2) void gates_fused(
    const float* __restrict__ b_i, const float* __restrict__ b_o,
    const float* __restrict__ b_u, float* __restrict__ out)
{
    extern __shared__ char dsm[];
    const int tid = threadIdx.x, lane = tid & 31, warp = tid >> 5;
    const int b0 = blockIdx.x * 32, g0 = blockIdx.y * 128;
    const uint32_t smb = smem_u32(dsm);
    const int tIdx = lane >> 3, rsub = lane & 7;

    // stage A (comb hi+lo, 32 batches x 512 k) — shares commit group with B chunk 0
    for (int i = tid; i < 4096; i += 256) {
        int hl = i >> 11, j = i & 2047;
        int s = j >> 6, q = j & 63;
        const __half* src = (hl ? g_combL : g_combH) + (size_t)(b0 + s) * 512 + q * 8;
        cpa16(dsm + hl * GA_LO + (s * GASTR + q * 8) * 2, src);
    }

    // B chunk c: gate = c>>4, kc = c&15 (32 k each), 128 n rows (this ghalf)
    auto stageB = [&](int c, int buf) {
        int gate = c >> 4, kc = c & 15;
        for (int i = tid; i < 1024; i += 256) {
            int hl = i >> 9, j = i & 511;
            int n = j >> 2, q = j & 3;
            const __half* src = (hl ? g_WgL : g_WgH) +
                ((size_t)gate * 256 + g0 + n) * 512 + kc * 32 + q * 8;
            cpa16(dsm + GB_OFF(buf, hl) + (n * GBSTR + q * 8) * 2, src);
        }
        CPA_COMMIT();
    };

    stageB(0, 0);

    float d[3][2][2][4];
    #pragma unroll
    for (int gt = 0; gt < 3; gt++)
        #pragma unroll
        for (int mt = 0; mt < 2; mt++)
            #pragma unroll
            for (int nt = 0; nt < 2; nt++)
                #pragma unroll
                for (int q = 0; q < 4; q++) d[gt][mt][nt][q] = 0.0f;

    #pragma unroll 1
    for (int c = 0; c < 48; c++) {
        int buf = c & 1;
        if (c < 47) stageB(c + 1, buf ^ 1);
        else CPA_COMMIT();
        cpa_wait<1>();
        __syncthreads();

        int gate = c >> 4, kc = c & 15;
        float* dg = &d[gate][0][0][0];
        #pragma unroll
        for (int kt = 0; kt < 2; kt++) {
            int kk = kc * 32 + kt * 16;
            uint32_t ah[2][4], al[2][4], bh[4], bl[4];
            #pragma unroll
            for (int mt = 0; mt < 2; mt++) {
                int row = mt * 16 + ((tIdx & 1) ? 8 : 0) + rsub;
                int col = kk + ((tIdx & 2) ? 8 : 0);
                ldsm4(ah[mt], smb + (uint32_t)(row * GASTR + col) * 2u);
                ldsm4(al[mt], smb + GA_LO + (uint32_t)(row * GASTR + col) * 2u);
            }
            {
                int n = warp * 16 + ((tIdx & 2) ? 8 : 0) + rsub;
                int k = kt * 16 + ((tIdx & 1) ? 8 : 0);
                ldsm4(bh, smb + GB_OFF(buf, 0) + (uint32_t)(n * GBSTR + k) * 2u);
                ldsm4(bl, smb + GB_OFF(buf, 1) + (uint32_t)(n * GBSTR + k) * 2u);
            }
            #pragma unroll
            for (int mt = 0; mt < 2; mt++)
                #pragma unroll
                for (int nt = 0; nt < 2; nt++) {
                    float* dd = dg + (mt * 2 + nt) * 4;
                    mma16816h(dd, ah[mt], &bh[nt * 2]);
                    mma16816h(dd, al[mt], &bh[nt * 2]);
                    mma16816h(dd, ah[mt], &bl[nt * 2]);
                }
        }
        __syncthreads();
    }
    cpa_wait<0>();

    // ---- inline epilogue: biases + csum6 + activations -> out ----
    {
        int arow = lane >> 2, acol = (lane & 3) * 2;
        #pragma unroll
        for (int mt = 0; mt < 2; mt++)
            #pragma unroll
            for (int ro = 0; ro < 2; ro++) {
                int bA = b0 + mt * 16 + arow + ro * 8;
                #pragma unroll
                for (int nt = 0; nt < 2; nt++) {
                    int gc = g0 + warp * 16 + nt * 8 + acol;
                    float2 bi2 = *(const float2*)&b_i[gc];
                    float2 bo2 = *(const float2*)&b_o[gc];
                    float2 bu2 = *(const float2*)&b_u[gc];
                    float2 cs = make_float2(0.f, 0.f);
                    #pragma unroll
                    for (int slot = 0; slot < 6; slot++) {
                        float2 v = *(const float2*)
                            &g_csum6[((size_t)slot * BB + bA) * HH + gc];
                        cs.x += v.x; cs.y += v.y;
                    }
                    #pragma unroll
                    for (int e = 0; e < 2; e++) {
                        int q = ro * 2 + e;
                        float pi = d[0][mt][nt][q] + (e ? bi2.y : bi2.x);
                        float po = d[1][mt][nt][q] + (e ? bo2.y : bo2.x);
                        float pu = d[2][mt][nt][q] + (e ? bu2.y : bu2.x);
                        float iv = 1.0f / (1.0f + expf(-pi));
                        float ov = 1.0f / (1.0f + expf(-po));
                        float uv = tanhf(pu);
                        float cv = fmaf(iv, uv, e ? cs.y : cs.x);
                        float hv = ov * tanhf(cv);
                        out[(size_t)bA * HH + gc + e]            = hv;  // h
                        out[(size_t)(BB + bA) * HH + gc + e]     = cv;  // c
                    }
                }
            }
    }
}

// ---------------- launch ----------------
extern "C" void kernel_launch(void* const* d_in, const int* in_sizes, int n_in,
                              void* d_out, int out_size) {
    const float* input_vec = (const float*)d_in[0];
    const float* child_h   = (const float*)d_in[1];
    const float* child_c   = (const float*)d_in[2];
    const int*   rid       = (const int*)d_in[3];
    const int*   vmask     = (const int*)d_in[4];
    const float* rel_emb   = (const float*)d_in[5];
    const float* W_i = (const float*)d_in[6];
    const float* b_i = (const float*)d_in[7];
    const float* W_f = (const float*)d_in[8];
    const float* b_f = (const float*)d_in[9];
    const float* W_o = (const float*)d_in[10];
    const float* b_o = (const float*)d_in[11];
    const float* W_u = (const float*)d_in[12];
    const float* b_u = (const float*)d_in[13];
    const float* w_att = (const float*)d_in[14];
    const float* b_att = (const float*)d_in[15];
    float* out = (float*)d_out;

    cudaFuncSetAttribute(fgemm_mma,   cudaFuncAttributeMaxDynamicSharedMemorySize, FG_DYN);
    cudaFuncSetAttribute(gates_fused, cudaFuncAttributeMaxDynamicSharedMemorySize, GF_DYN);

    prep_kernel<<<2304, 256>>>(W_i, W_o, W_u, W_f);
    attn_kernel<<<BB, 256>>>(input_vec, child_h, rid, vmask, rel_emb, w_att, b_att);
    dim3 fg(BB / 16, RR, 4);
    fgemm_mma<<<fg, 256, FG_DYN>>>(child_c, rid, vmask, b_f);
    dim3 gg(BB / 32, 2);
    gates_fused<<<gg, 256, GF_DYN>>>(b_i, b_o, b_u, out);
}

// round 17
// speedup vs baseline: 1.0992x; 1.0992x over previous
#include <cuda_runtime.h>
#include <cuda_fp16.h>
#include <cstdint>
#include <math.h>

#define BB 4096
#define NN 32
#define HH 256
#define RR 3
#define VDECAY 0.7f

// ---------------- device scratch ----------------
__device__ float  g_csum6[6 * BB * HH];        // [r*2+khalf][b][g] partial csum
__device__ float  g_pre[3 * BB * HH];          // gate preacts [gate][b][g]
__device__ __half g_chH[(size_t)BB * NN * HH]; // child_h fp16 (raw)
__device__ __half g_combH[BB * 512];           // comb fp16 hi
__device__ __half g_combL[BB * 512];           // comb fp16 lo
__device__ __half g_WfH[RR * HH * HH];         // W_f fp16 hi
__device__ __half g_WfL[RR * HH * HH];         // W_f fp16 lo
__device__ __half g_WgH[3 * HH * 512];         // gate W fp16 hi [gate][g][k]
__device__ __half g_WgL[3 * HH * 512];         // gate W fp16 lo

// ---------------- helpers ----------------
__device__ __forceinline__ uint32_t smem_u32(const void* p) {
    uint32_t a;
    asm("{ .reg .u64 t; cvta.to.shared.u64 t, %1; cvt.u32.u64 %0, t; }" : "=r"(a) : "l"(p));
    return a;
}
__device__ __forceinline__ void ldsm4(uint32_t* r, uint32_t addr) {
    asm volatile("ldmatrix.sync.aligned.m8n8.x4.shared.b16 {%0,%1,%2,%3}, [%4];"
                 : "=r"(r[0]), "=r"(r[1]), "=r"(r[2]), "=r"(r[3]) : "r"(addr));
}
__device__ __forceinline__ void mma16816h(float* d, const uint32_t* a, const uint32_t* b) {
    asm volatile("mma.sync.aligned.m16n8k16.row.col.f32.f16.f16.f32 "
                 "{%0,%1,%2,%3},{%4,%5,%6,%7},{%8,%9},{%0,%1,%2,%3};"
                 : "+f"(d[0]), "+f"(d[1]), "+f"(d[2]), "+f"(d[3])
                 : "r"(a[0]), "r"(a[1]), "r"(a[2]), "r"(a[3]), "r"(b[0]), "r"(b[1]));
}
__device__ __forceinline__ uint32_t pkhf(float x, float y) {
    __half2 t = __floats2half2_rn(x, y);
    return *(uint32_t*)&t;
}
__device__ __forceinline__ void cpa16(void* sdst, const void* gsrc) {
    unsigned s = (unsigned)__cvta_generic_to_shared(sdst);
    asm volatile("cp.async.ca.shared.global [%0], [%1], 16;" :: "r"(s), "l"(gsrc) : "memory");
}
#define CPA_COMMIT() asm volatile("cp.async.commit_group;" ::: "memory")
template <int N> __device__ __forceinline__ void cpa_wait() {
    asm volatile("cp.async.wait_group %0;" :: "n"(N) : "memory");
}

// ---------------- prep: fp16 splits for W_f and gate weights ----------------
__global__ void prep_kernel(const float* __restrict__ Wi,
                            const float* __restrict__ Wo,
                            const float* __restrict__ Wu,
                            const float* __restrict__ Wf) {
    int idx = blockIdx.x * blockDim.x + threadIdx.x;
    const int NWG = 3 * HH * 512;
    const int NF  = RR * HH * HH;
    if (idx < NWG) {
        int j = idx & (HH * 512 - 1);
        int gate = idx >> 17;
        const float* W = (gate == 0) ? Wi : ((gate == 1) ? Wo : Wu);
        float v = W[j];
        __half h = __float2half_rn(v);
        g_WgH[idx] = h;
        g_WgL[idx] = __float2half_rn(v - __half2float(h));
    } else if (idx < NWG + NF) {
        int j = idx - NWG;
        float v = Wf[j];
        __half h = __float2half_rn(v);
        g_WfH[j] = h;
        g_WfL[j] = __float2half_rn(v - __half2float(h));
    }
}

// ---------------- attention + comb + fp16 conversions (validated R15) ----------------
#define CHS 260
__global__ __launch_bounds__(256) void attn_kernel(
    const float* __restrict__ input_vec, const float* __restrict__ child_h,
    const int* __restrict__ relation_ids, const int* __restrict__ virtual_mask,
    const float* __restrict__ rel_emb, const float* __restrict__ w_att,
    const float* __restrict__ b_att)
{
    __shared__ float sh_ch[NN * CHS];
    __shared__ int   sh_rid[NN];
    __shared__ float sh_decay[NN], sh_score[NN], sh_attn[NN];
    const int b = blockIdx.x, tid = threadIdx.x, lane = tid & 31, warp = tid >> 5;

    if (tid < NN) {
        sh_rid[tid]   = relation_ids[b * NN + tid];
        sh_decay[tid] = virtual_mask[b * NN + tid] ? VDECAY : 1.0f;
    }
    __syncthreads();
    {
        const float* chb = child_h + (size_t)b * NN * HH;
        uint32_t* chH2 = (uint32_t*)(g_chH + (size_t)b * NN * HH);
        for (int i2 = tid; i2 < NN * 128; i2 += 256) {
            int n = i2 >> 7, h2 = (i2 & 127) * 2;
            float2 v = *(const float2*)(chb + n * HH + h2);
            float d = sh_decay[n];
            sh_ch[n * CHS + h2]     = v.x * d;
            sh_ch[n * CHS + h2 + 1] = v.y * d;
            chH2[i2] = pkhf(v.x, v.y);
        }
    }
    __syncthreads();
    {
        float batt = b_att[0];
        #pragma unroll
        for (int c = 0; c < 4; c++) {
            int p = warp * 4 + c;
            int r = sh_rid[p];
            float s = 0.0f;
            #pragma unroll
            for (int j = 0; j < 8; j++) {
                int h = j * 32 + lane;
                s = fmaf(rel_emb[r * HH + h] + sh_ch[p * CHS + h], w_att[h], s);
            }
            #pragma unroll
            for (int off = 16; off; off >>= 1) s += __shfl_xor_sync(0xffffffffu, s, off);
            if (lane == 0) sh_score[p] = s + batt;
        }
    }
    __syncthreads();
    if (warp == 0) {
        float v = sh_score[lane], m = v;
        #pragma unroll
        for (int off = 16; off; off >>= 1) m = fmaxf(m, __shfl_xor_sync(0xffffffffu, m, off));
        float e = expf(v - m), s = e;
        #pragma unroll
        for (int off = 16; off; off >>= 1) s += __shfl_xor_sync(0xffffffffu, s, off);
        sh_attn[lane] = e / s;
    }
    __syncthreads();
    const int g = tid;
    float hs = 0.0f;
    #pragma unroll
    for (int p = 0; p < NN; p++) hs = fmaf(sh_attn[p], sh_ch[p * CHS + g], hs);
    float inv = input_vec[(size_t)b * HH + g];
    __half ih = __float2half_rn(inv);
    __half hh = __float2half_rn(hs);
    g_combH[b * 512 + g]       = ih;
    g_combL[b * 512 + g]       = __float2half_rn(inv - __half2float(ih));
    g_combH[b * 512 + 256 + g] = hh;
    g_combL[b * 512 + 256 + g] = __float2half_rn(hs - __half2float(hh));
}

// ---------------- fgemm_mma: BT=32, fp16 2-term, cp.async pipelined ----------
// grid (128, 3, 4): z = khalf*2 + ghalf. block 256 = 8 warps, 2 CTAs/SM.
#define BT 32
#define BSTR 136
#define BL_OFF 34816
#define AB_OFF(buf) ((buf) * 8704)
#define F_OFF 17408
#define FSTR 132
#define FG_DYN 69632

__global__ __launch_bounds__(256, 2) void fgemm_mma(
    const float* __restrict__ child_c,
    const int*   __restrict__ relation_ids,
    const int*   __restrict__ virtual_mask,
    const float* __restrict__ b_f)
{
    extern __shared__ char dsm[];
    __shared__ int   sList[BT * NN], sStart[BT + 1], sCnt[BT];
    __shared__ float shCS[2][BT][129];

    const int tid = threadIdx.x, lane = tid & 31, warp = tid >> 5;
    const int b0 = blockIdx.x * BT, r = blockIdx.y;
    const int ghalf = blockIdx.z & 1, khalf = blockIdx.z >> 1;
    const int g0 = ghalf * 128, k0 = khalf * 128;

    if (tid < BT) {
        int c = 0;
        for (int n = 0; n < 32; n++) c += (relation_ids[(b0 + tid) * NN + n] == r);
        sCnt[tid] = c;
    }
    for (int i = tid; i < 2 * BT * 129; i += 256) ((float*)shCS)[i] = 0.0f;
    __syncthreads();
    if (tid == 0) {
        int a = 0;
        for (int i = 0; i < BT; i++) { sStart[i] = a; a += sCnt[i]; }
        sStart[BT] = a;
    }
    __syncthreads();
    if (tid < BT) {
        int pos = sStart[tid];
        for (int n = 0; n < 32; n++) {
            if (relation_ids[(b0 + tid) * NN + n] == r) {
                int v = virtual_mask[(b0 + tid) * NN + n] ? 1 : 0;
                sList[pos++] = n | (v << 6) | (tid << 8);
            }
        }
    }
    __syncthreads();

    for (int j = tid; j < 4096; j += 256) {
        int hl = j >> 11, jj = j & 2047;
        int gg = jj >> 4, q = jj & 15;
        const __half* src = (hl ? g_WfL : g_WfH) +
            (size_t)r * 65536 + (size_t)(g0 + gg) * 256 + k0 + q * 8;
        cpa16(dsm + hl * BL_OFF + (gg * BSTR + q * 8) * 2, src);
    }
    CPA_COMMIT();
    cpa_wait<0>();
    __syncthreads();

    const int count = sStart[BT];
    const int ntiles = (count + 31) >> 5;
    const uint32_t smb = smem_u32(dsm);
    const int gcol = tid & 127, hf = tid >> 7;
    const float bfk = (khalf == 0) ? b_f[r * HH + g0 + gcol] : 0.0f;
    const int tIdx = lane >> 3, rsub = lane & 7;

    uint32_t bhreg[8][4];
    {
        int n = warp * 16 + ((tIdx & 2) ? 8 : 0) + rsub;
        #pragma unroll
        for (int kt = 0; kt < 8; kt++) {
            int k = kt * 16 + ((tIdx & 1) ? 8 : 0);
            ldsm4(bhreg[kt], smb + (uint32_t)(n * BSTR + k) * 2u);
        }
    }
    __syncthreads();

    auto stageA = [&](int tt, int buf) {
        for (int i = tid; i < 512; i += 256) {
            int s = i >> 4, q = i & 15;
            int gs = tt * 32 + s;
            if (gs < count) {
                int e = sList[gs];
                const __half* src = g_chH +
                    (((size_t)(b0 + (e >> 8))) * NN + (e & 63)) * HH + k0 + q * 8;
                cpa16(dsm + AB_OFF(buf) + (s * BSTR + q * 8) * 2, src);
            }
        }
        CPA_COMMIT();
    };

    if (ntiles > 0) stageA(0, 0);

    for (int t = 0; t < ntiles; t++) {
        const int buf = t & 1;
        cpa_wait<0>();
        __syncthreads();

        if (t + 1 < ntiles) stageA(t + 1, buf ^ 1);

        float ccv[16];
        {
            int sbase = t * 32 + hf * 16;
            #pragma unroll
            for (int j = 0; j < 16; j++) {
                int s = sbase + j;
                float v = 0.0f;
                if (s < count) {
                    int e = sList[s];
                    v = child_c[((size_t)(b0 + (e >> 8)) * NN + (e & 63)) * HH + g0 + gcol];
                }
                ccv[j] = v;
            }
        }

        float d[2][2][4];
        #pragma unroll
        for (int mt = 0; mt < 2; mt++)
            #pragma unroll
            for (int nt = 0; nt < 2; nt++)
                #pragma unroll
                for (int q = 0; q < 4; q++) d[mt][nt][q] = 0.0f;
        {
            const uint32_t ahb = smb + AB_OFF(buf);
            const uint32_t blb = smb + BL_OFF;
            int brow = warp * 16 + ((tIdx & 2) ? 8 : 0) + rsub;
            #pragma unroll
            for (int kt = 0; kt < 8; kt++) {
                int kk = kt * 16;
                int kfrag = kk + ((tIdx & 1) ? 8 : 0);
                uint32_t areg[2][4], blreg[4];
                #pragma unroll
                for (int mt = 0; mt < 2; mt++) {
                    int row = mt * 16 + ((tIdx & 1) ? 8 : 0) + rsub;
                    int col = kk + ((tIdx & 2) ? 8 : 0);
                    ldsm4(areg[mt], ahb + (uint32_t)(row * BSTR + col) * 2u);
                }
                ldsm4(blreg, blb + (uint32_t)(brow * BSTR + kfrag) * 2u);
                #pragma unroll
                for (int mt = 0; mt < 2; mt++)
                    #pragma unroll
                    for (int nt = 0; nt < 2; nt++) {
                        mma16816h(d[mt][nt], areg[mt], &bhreg[kt][nt * 2]);
                        mma16816h(d[mt][nt], areg[mt], &blreg[nt * 2]);
                    }
            }
        }

        {
            float* F = (float*)(dsm + F_OFF);
            int arow = lane >> 2, acol = (lane & 3) * 2;
            #pragma unroll
            for (int mt = 0; mt < 2; mt++)
                #pragma unroll
                for (int nt = 0; nt < 2; nt++) {
                    int col = warp * 16 + nt * 8 + acol;
                    F[(mt * 16 + arow) * FSTR + col]         = d[mt][nt][0];
                    F[(mt * 16 + arow) * FSTR + col + 1]     = d[mt][nt][1];
                    F[(mt * 16 + arow + 8) * FSTR + col]     = d[mt][nt][2];
                    F[(mt * 16 + arow + 8) * FSTR + col + 1] = d[mt][nt][3];
                }
        }
        __syncthreads();

        {
            const float* F = (const float*)(dsm + F_OFF);
            int sbase = t * 32 + hf * 16;
            int smax = min(16, count - sbase);
            for (int j = 0; j < smax; j++) {
                int e = sList[sbase + j];
                int bl = e >> 8;
                float dcy = ((e >> 6) & 1) ? VDECAY : 1.0f;
                float Fv = F[(hf * 16 + j) * FSTR + gcol];
                shCS[hf][bl][gcol] += (Fv * dcy + bfk) * (ccv[j] * dcy);
            }
        }
    }

    {
        int slot = r * 2 + khalf;
        __syncthreads();
        for (int i = tid; i < BT * 128; i += 256) {
            int bl = i >> 7, g = i & 127;
            g_csum6[((size_t)slot * BB + b0 + bl) * HH + g0 + g] =
                shCS[0][bl][g] + shCS[1][bl][g];
        }
    }
}

// ---------------- gates_mma: HMMA gate GEMM, 3-term split (validated R15) ----
#define ASTR 520
#define GA_LO 33280
#define GB(buf, hl) (66560 + (buf) * 73728 + (hl) * 36864)
#define GBSTR 72
#define GG_DYN 214016

__global__ __launch_bounds__(256) void gates_mma() {
    extern __shared__ char dsm[];
    const int tid = threadIdx.x, lane = tid & 31, warp = tid >> 5;
    const int b0 = blockIdx.x * 32, gate = blockIdx.y;
    const uint32_t smb = smem_u32(dsm);
    const int tIdx = lane >> 3, rsub = lane & 7;

    for (int i = tid; i < 4096; i += 256) {
        int hl = i >> 11, j = i & 2047;
        int s = j >> 6, q = j & 63;
        const __half* src = (hl ? g_combL : g_combH) + (size_t)(b0 + s) * 512 + q * 8;
        cpa16(dsm + hl * GA_LO + (s * ASTR + q * 8) * 2, src);
    }

    auto stageB = [&](int kc, int buf) {
        for (int i = tid; i < 4096; i += 256) {
            int hl = i >> 11, j = i & 2047;
            int n = j >> 3, q = j & 7;
            const __half* src = (hl ? g_WgL : g_WgH) +
                ((size_t)gate * 256 + n) * 512 + kc * 64 + q * 8;
            cpa16(dsm + GB(buf, hl) + (n * GBSTR + q * 8) * 2, src);
        }
        CPA_COMMIT();
    };

    stageB(0, 0);

    float d[2][4][4];
    #pragma unroll
    for (int mt = 0; mt < 2; mt++)
        #pragma unroll
        for (int nq = 0; nq < 4; nq++)
            #pragma unroll
            for (int q = 0; q < 4; q++) d[mt][nq][q] = 0.0f;

    #pragma unroll 1
    for (int kc = 0; kc < 8; kc++) {
        int buf = kc & 1;
        if (kc < 7) stageB(kc + 1, buf ^ 1);
        else CPA_COMMIT();
        cpa_wait<1>();
        __syncthreads();

        #pragma unroll
        for (int ks = 0; ks < 4; ks++) {
            int kk = ks * 16;
            uint32_t ah[2][4], al[2][4], bh[2][4], bl[2][4];
            #pragma unroll
            for (int mt = 0; mt < 2; mt++) {
                int row = mt * 16 + ((tIdx & 1) ? 8 : 0) + rsub;
                int col = kc * 64 + kk + ((tIdx & 2) ? 8 : 0);
                ldsm4(ah[mt], smb + (uint32_t)(row * ASTR + col) * 2u);
                ldsm4(al[mt], smb + GA_LO + (uint32_t)(row * ASTR + col) * 2u);
            }
            #pragma unroll
            for (int ng = 0; ng < 2; ng++) {
                int n = warp * 32 + ng * 16 + ((tIdx & 2) ? 8 : 0) + rsub;
                int k = kk + ((tIdx & 1) ? 8 : 0);
                ldsm4(bh[ng], smb + GB(buf, 0) + (uint32_t)(n * GBSTR + k) * 2u);
                ldsm4(bl[ng], smb + GB(buf, 1) + (uint32_t)(n * GBSTR + k) * 2u);
            }
            #pragma unroll
            for (int mt = 0; mt < 2; mt++)
                #pragma unroll
                for (int ng = 0; ng < 2; ng++)
                    #pragma unroll
                    for (int sub = 0; sub < 2; sub++) {
                        float* dd = d[mt][ng * 2 + sub];
                        mma16816h(dd, ah[mt], &bh[ng][sub * 2]);
                        mma16816h(dd, al[mt], &bh[ng][sub * 2]);
                        mma16816h(dd, ah[mt], &bl[ng][sub * 2]);
                    }
        }
        __syncthreads();
    }
    cpa_wait<0>();

    {
        int arow = lane >> 2, acol = (lane & 3) * 2;
        #pragma unroll
        for (int mt = 0; mt < 2; mt++)
            #pragma unroll
            for (int nq = 0; nq < 4; nq++) {
                int gcol = warp * 32 + nq * 8 + acol;
                int bA = b0 + mt * 16 + arow;
                float* p = g_pre + ((size_t)gate * BB) * HH;
                *(float2*)&p[(size_t)bA * HH + gcol] = make_float2(d[mt][nq][0], d[mt][nq][1]);
                *(float2*)&p[(size_t)(bA + 8) * HH + gcol] = make_float2(d[mt][nq][2], d[mt][nq][3]);
            }
    }
}

// ---------------- epilogue: biases + csum + activations (validated R15) ----
__global__ __launch_bounds__(256) void epi_kernel(
    const float* __restrict__ b_i, const float* __restrict__ b_o,
    const float* __restrict__ b_u, float* __restrict__ out)
{
    const int b = blockIdx.x, g = threadIdx.x;
    size_t idx = (size_t)b * HH + g;
    float cs = 0.0f;
    #pragma unroll
    for (int slot = 0; slot < 6; slot++)
        cs += g_csum6[(size_t)slot * BB * HH + idx];
    float pi = g_pre[idx]                       + b_i[g];
    float po = g_pre[(size_t)BB * HH + idx]     + b_o[g];
    float pu = g_pre[(size_t)2 * BB * HH + idx] + b_u[g];
    float iv = 1.0f / (1.0f + expf(-pi));
    float ov = 1.0f / (1.0f + expf(-po));
    float uv = tanhf(pu);
    float cv = fmaf(iv, uv, cs);
    float hv = ov * tanhf(cv);
    out[idx]                   = hv;   // h first
    out[(size_t)BB * HH + idx] = cv;   // then c
}

// ---------------- launch ----------------
extern "C" void kernel_launch(void* const* d_in, const int* in_sizes, int n_in,
                              void* d_out, int out_size) {
    const float* input_vec = (const float*)d_in[0];
    const float* child_h   = (const float*)d_in[1];
    const float* child_c   = (const float*)d_in[2];
    const int*   rid       = (const int*)d_in[3];
    const int*   vmask     = (const int*)d_in[4];
    const float* rel_emb   = (const float*)d_in[5];
    const float* W_i = (const float*)d_in[6];
    const float* b_i = (const float*)d_in[7];
    const float* W_f = (const float*)d_in[8];
    const float* b_f = (const float*)d_in[9];
    const float* W_o = (const float*)d_in[10];
    const float* b_o = (const float*)d_in[11];
    const float* W_u = (const float*)d_in[12];
    const float* b_u = (const float*)d_in[13];
    const float* w_att = (const float*)d_in[14];
    const float* b_att = (const float*)d_in[15];
    float* out = (float*)d_out;

    cudaFuncSetAttribute(fgemm_mma, cudaFuncAttributeMaxDynamicSharedMemorySize, FG_DYN);
    cudaFuncSetAttribute(gates_mma, cudaFuncAttributeMaxDynamicSharedMemorySize, GG_DYN);

    prep_kernel<<<2304, 256>>>(W_i, W_o, W_u, W_f);
    attn_kernel<<<BB, 256>>>(input_vec, child_h, rid, vmask, rel_emb, w_att, b_att);
    dim3 fg(BB / BT, RR, 4);
    fgemm_mma<<<fg, 256, FG_DYN>>>(child_c, rid, vmask, b_f);
    dim3 gg(BB / 32, 3);
    gates_mma<<<gg, 256, GG_DYN>>>();
    epi_kernel<<<BB, 256>>>(b_i, b_o, b_u, out);
}